// round 1
// baseline (speedup 1.0000x reference)
#include <cuda_runtime.h>

#define B_ 8
#define T_ 12
#define N_ 1024
#define C_ 64
#define H_ 8
#define D_ 64
#define HD_ 512
#define BT_ 96
#define EPSV 1e-3f

// ---------------- scratch (device globals; no allocation) ----------------
__device__ float g_q[BT_ * HD_];
__device__ float g_k[BT_ * HD_];
__device__ float g_w[H_ * B_ * T_ * T_];
__device__ float g_agg[B_ * T_ * N_ * C_];          // 25 MB
__device__ float g_v[B_ * T_ * N_ * HD_];           // 201 MB (v, then update in-place)
__device__ double g_part[B_ * 96 * 2];
__device__ float g_stats[B_ * 4];                   // per-b: mean_s, rstd_s, mean_g, rstd_g

// ---------------- 1) q/k projections: [96,1024]@[1024,512] ----------------
__global__ void qk_kernel(const float* __restrict__ state,
                          const float* __restrict__ Wq, const float* __restrict__ bq,
                          const float* __restrict__ Wk, const float* __restrict__ bk) {
    __shared__ float s[N_];
    int bt = blockIdx.x;
    for (int i = threadIdx.x; i < N_; i += blockDim.x) s[i] = state[bt * N_ + i];
    __syncthreads();
    int hd = threadIdx.x;  // 512 threads
    float qa = 0.f, ka = 0.f;
#pragma unroll 4
    for (int m = 0; m < N_; m++) {
        float sv = s[m];
        qa = fmaf(sv, Wq[m * HD_ + hd], qa);
        ka = fmaf(sv, Wk[m * HD_ + hd], ka);
    }
    g_q[bt * HD_ + hd] = qa + bq[hd];
    g_k[bt * HD_ + hd] = ka + bk[hd];
}

// ---------------- 2) attention weights: 12x12 softmax per (h,b) ----------------
__global__ void attw_kernel() {
    __shared__ float sc[T_][T_];
    int b = blockIdx.x % B_;
    int h = blockIdx.x / B_;
    int t = threadIdx.x;
    int i = t / T_, j = t % T_;
    if (t < T_ * T_) {
        const float* qp = &g_q[(b * T_ + i) * HD_ + h * D_];
        const float* kp = &g_k[(b * T_ + j) * HD_ + h * D_];
        float d = 0.f;
#pragma unroll
        for (int x = 0; x < D_; x++) d = fmaf(qp[x], kp[x], d);
        sc[i][j] = d * 0.125f;  // / sqrt(64)
    }
    __syncthreads();
    if (t < T_ * T_) {
        float mx = -1e30f;
#pragma unroll
        for (int x = 0; x < T_; x++) mx = fmaxf(mx, sc[i][x]);
        float sm = 0.f;
#pragma unroll
        for (int x = 0; x < T_; x++) sm += expf(sc[i][x] - mx);
        g_w[((h * B_ + b) * T_ + i) * T_ + j] = expf(sc[i][j] - mx) / sm;
    }
}

// ---------------- generic 128x64 tile SGEMM body (TK=16, 256 thr, 8x4 micro) ----
// 3) agg[bt] = adj @ signal[bt] : M=1024, Ncols=64, K=1024
__global__ void agg_kernel(const float* __restrict__ adj, const float* __restrict__ sig) {
    __shared__ float As[16][132];
    __shared__ float Bs[16][64];
    int n0 = blockIdx.x * 128;
    int bt = blockIdx.y;
    int tid = threadIdx.x;
    int tx = tid & 15, ty = tid >> 4;
    float acc[8][4];
#pragma unroll
    for (int i = 0; i < 8; i++)
#pragma unroll
        for (int j = 0; j < 4; j++) acc[i][j] = 0.f;
    const float* sigb = sig + bt * (N_ * C_);
    for (int k0 = 0; k0 < N_; k0 += 16) {
#pragma unroll
        for (int p = 0; p < 8; p++) {
            int e = tid + p * 256;
            int k = e & 15, n = e >> 4;
            As[k][n] = adj[(n0 + n) * N_ + k0 + k];
        }
#pragma unroll
        for (int p = 0; p < 4; p++) {
            int e = tid + p * 256;
            int c = e & 63, k = e >> 6;
            Bs[k][c] = sigb[(k0 + k) * C_ + c];
        }
        __syncthreads();
#pragma unroll
        for (int kk = 0; kk < 16; kk++) {
            float4 a0 = *(const float4*)&As[kk][ty * 8];
            float4 a1 = *(const float4*)&As[kk][ty * 8 + 4];
            float4 bv = *(const float4*)&Bs[kk][tx * 4];
            float a[8] = {a0.x, a0.y, a0.z, a0.w, a1.x, a1.y, a1.z, a1.w};
            float bb[4] = {bv.x, bv.y, bv.z, bv.w};
#pragma unroll
            for (int i = 0; i < 8; i++)
#pragma unroll
                for (int j = 0; j < 4; j++) acc[i][j] = fmaf(a[i], bb[j], acc[i][j]);
        }
        __syncthreads();
    }
    float* outb = g_agg + bt * (N_ * C_);
#pragma unroll
    for (int i = 0; i < 8; i++) {
        int n = n0 + ty * 8 + i;
#pragma unroll
        for (int j = 0; j < 4; j++) outb[n * C_ + tx * 4 + j] = acc[i][j];
    }
}

// 4) v[bt] = agg[bt] @ Kg[t] + bg[t] : M=1024, Ncols=512, K=64
__global__ void v_kernel(const float* __restrict__ Kg, const float* __restrict__ bg) {
    __shared__ float As[16][132];
    __shared__ float Bs[16][64];
    int n0 = blockIdx.x * 128;
    int m0 = blockIdx.y * 64;
    int bt = blockIdx.z;
    int t = bt % T_;
    int tid = threadIdx.x;
    int tx = tid & 15, ty = tid >> 4;
    float acc[8][4];
#pragma unroll
    for (int i = 0; i < 8; i++)
#pragma unroll
        for (int j = 0; j < 4; j++) acc[i][j] = 0.f;
    const float* aggb = g_agg + bt * (N_ * C_);
    const float* Kgt = Kg + t * (C_ * HD_);
    for (int k0 = 0; k0 < C_; k0 += 16) {
#pragma unroll
        for (int p = 0; p < 8; p++) {
            int e = tid + p * 256;
            int k = e & 15, n = e >> 4;
            As[k][n] = aggb[(n0 + n) * C_ + k0 + k];
        }
#pragma unroll
        for (int p = 0; p < 4; p++) {
            int e = tid + p * 256;
            int m = e & 63, k = e >> 6;
            Bs[k][m] = Kgt[(k0 + k) * HD_ + m0 + m];
        }
        __syncthreads();
#pragma unroll
        for (int kk = 0; kk < 16; kk++) {
            float4 a0 = *(const float4*)&As[kk][ty * 8];
            float4 a1 = *(const float4*)&As[kk][ty * 8 + 4];
            float4 bv = *(const float4*)&Bs[kk][tx * 4];
            float a[8] = {a0.x, a0.y, a0.z, a0.w, a1.x, a1.y, a1.z, a1.w};
            float bb[4] = {bv.x, bv.y, bv.z, bv.w};
#pragma unroll
            for (int i = 0; i < 8; i++)
#pragma unroll
                for (int j = 0; j < 4; j++) acc[i][j] = fmaf(a[i], bb[j], acc[i][j]);
        }
        __syncthreads();
    }
    float* outb = g_v + bt * (N_ * HD_);
#pragma unroll
    for (int i = 0; i < 8; i++) {
        int n = n0 + ty * 8 + i;
#pragma unroll
        for (int j = 0; j < 4; j++) {
            int m = m0 + tx * 4 + j;
            outb[n * HD_ + m] = acc[i][j] + bg[t * HD_ + m];
        }
    }
}

// 5) attention mix, IN-PLACE on g_v: update[b,q,n,m] = sum_k w[h(m),b,q,k]*v[b,k,n,m]
__global__ void upd_kernel() {
    __shared__ float sw[H_ * T_ * T_];  // 1152 floats for this b
    int b = blockIdx.z;
    int n = blockIdx.y;
    int m = blockIdx.x * 128 + threadIdx.x;
    for (int i = threadIdx.x; i < H_ * T_ * T_; i += 128) {
        int h = i / (T_ * T_);
        int r = i % (T_ * T_);
        sw[i] = g_w[(h * B_ + b) * (T_ * T_) + r];
    }
    __syncthreads();
    int h = m >> 6;
    int base = (b * T_) * (N_ * HD_) + n * HD_ + m;
    float vv[T_];
#pragma unroll
    for (int k = 0; k < T_; k++) vv[k] = g_v[base + k * (N_ * HD_)];
#pragma unroll
    for (int q = 0; q < T_; q++) {
        float a = 0.f;
#pragma unroll
        for (int k = 0; k < T_; k++) a = fmaf(sw[h * (T_ * T_) + q * T_ + k], vv[k], a);
        g_v[base + q * (N_ * HD_)] = a;
    }
}

// 6) signal projection + ReLU + residual: update[R,512] @ Wf[512,64]
__global__ void sigproj_kernel(const float* __restrict__ Wf, const float* __restrict__ bf,
                               const float* __restrict__ sig, float* __restrict__ out) {
    __shared__ float As[16][132];
    __shared__ float Bs[16][64];
    int r0 = blockIdx.x * 128;
    int tid = threadIdx.x;
    int tx = tid & 15, ty = tid >> 4;
    float acc[8][4];
#pragma unroll
    for (int i = 0; i < 8; i++)
#pragma unroll
        for (int j = 0; j < 4; j++) acc[i][j] = 0.f;
    for (int k0 = 0; k0 < HD_; k0 += 16) {
#pragma unroll
        for (int p = 0; p < 8; p++) {
            int e = tid + p * 256;
            int k = e & 15, n = e >> 4;
            As[k][n] = g_v[(r0 + n) * HD_ + k0 + k];
        }
#pragma unroll
        for (int p = 0; p < 4; p++) {
            int e = tid + p * 256;
            int c = e & 63, k = e >> 6;
            Bs[k][c] = Wf[(k0 + k) * C_ + c];
        }
        __syncthreads();
#pragma unroll
        for (int kk = 0; kk < 16; kk++) {
            float4 a0 = *(const float4*)&As[kk][ty * 8];
            float4 a1 = *(const float4*)&As[kk][ty * 8 + 4];
            float4 bv = *(const float4*)&Bs[kk][tx * 4];
            float a[8] = {a0.x, a0.y, a0.z, a0.w, a1.x, a1.y, a1.z, a1.w};
            float bb[4] = {bv.x, bv.y, bv.z, bv.w};
#pragma unroll
            for (int i = 0; i < 8; i++)
#pragma unroll
                for (int j = 0; j < 4; j++) acc[i][j] = fmaf(a[i], bb[j], acc[i][j]);
        }
        __syncthreads();
    }
#pragma unroll
    for (int i = 0; i < 8; i++) {
        int row = r0 + ty * 8 + i;
#pragma unroll
        for (int j = 0; j < 4; j++) {
            int c = tx * 4 + j;
            float y = fmaxf(acc[i][j] + bf[c], 0.f) + sig[row * C_ + c];
            out[row * C_ + c] = y;
        }
    }
}

// 7) state projection: warp per row, update[row,:] . Ws
__global__ void stateproj_kernel(const float* __restrict__ Ws, const float* __restrict__ bs,
                                 const float* __restrict__ state, float* __restrict__ outs) {
    int warp = (blockIdx.x * blockDim.x + threadIdx.x) >> 5;
    int lane = threadIdx.x & 31;
    if (warp >= BT_ * N_) return;
    const float* u = g_v + warp * HD_;
    float s = 0.f;
#pragma unroll
    for (int j = 0; j < HD_ / 32; j++) s = fmaf(u[lane + 32 * j], Ws[lane + 32 * j], s);
#pragma unroll
    for (int off = 16; off; off >>= 1) s += __shfl_down_sync(0xffffffffu, s, off);
    if (lane == 0) outs[warp] = state[warp] + fmaxf(s + bs[0], 0.f);
}

// ---------------- 8-10) deterministic LayerNorm statistics ----------------
__global__ void red_state_kernel(const float* __restrict__ ys) {
    __shared__ double ss[256], sq[256];
    int b = blockIdx.x;
    int tid = threadIdx.x;
    double s = 0, q = 0;
    for (int i = tid; i < T_ * N_; i += 256) {
        double x = ys[b * T_ * N_ + i];
        s += x; q += x * x;
    }
    ss[tid] = s; sq[tid] = q;
    __syncthreads();
    for (int o = 128; o; o >>= 1) {
        if (tid < o) { ss[tid] += ss[tid + o]; sq[tid] += sq[tid + o]; }
        __syncthreads();
    }
    if (tid == 0) {
        double cnt = (double)(T_ * N_);
        double mean = ss[0] / cnt;
        double var = sq[0] / cnt - mean * mean;
        g_stats[b * 4 + 0] = (float)mean;
        g_stats[b * 4 + 1] = rsqrtf((float)var + EPSV);
    }
}

__global__ void red_sig1_kernel(const float* __restrict__ yg) {
    __shared__ double ss[256], sq[256];
    int b = blockIdx.y, blk = blockIdx.x;
    int tid = threadIdx.x;
    const float* base = yg + b * (T_ * N_ * C_) + blk * 8192;
    double s = 0, q = 0;
    for (int i = tid; i < 8192; i += 256) {
        double x = base[i];
        s += x; q += x * x;
    }
    ss[tid] = s; sq[tid] = q;
    __syncthreads();
    for (int o = 128; o; o >>= 1) {
        if (tid < o) { ss[tid] += ss[tid + o]; sq[tid] += sq[tid + o]; }
        __syncthreads();
    }
    if (tid == 0) {
        g_part[(b * 96 + blk) * 2 + 0] = ss[0];
        g_part[(b * 96 + blk) * 2 + 1] = sq[0];
    }
}

__global__ void red_sig2_kernel() {
    __shared__ double ss[128], sq[128];
    int b = blockIdx.x;
    int tid = threadIdx.x;
    double s = 0, q = 0;
    if (tid < 96) {
        s = g_part[(b * 96 + tid) * 2 + 0];
        q = g_part[(b * 96 + tid) * 2 + 1];
    }
    ss[tid] = s; sq[tid] = q;
    __syncthreads();
    for (int o = 64; o; o >>= 1) {
        if (tid < o) { ss[tid] += ss[tid + o]; sq[tid] += sq[tid + o]; }
        __syncthreads();
    }
    if (tid == 0) {
        double cnt = (double)T_ * N_ * C_;
        double mean = ss[0] / cnt;
        double var = sq[0] / cnt - mean * mean;
        g_stats[b * 4 + 2] = (float)mean;
        g_stats[b * 4 + 3] = rsqrtf((float)var + EPSV);
    }
}

// ---------------- 11-12) in-place normalization ----------------
__global__ void norm_state_kernel(float* __restrict__ ys,
                                  const float* __restrict__ gamma,
                                  const float* __restrict__ beta) {
    int idx = blockIdx.x * 256 + threadIdx.x;
    int b = idx / (T_ * N_);
    int r = idx % (T_ * N_);
    float m = g_stats[b * 4 + 0];
    float rs = g_stats[b * 4 + 1];
    ys[idx] = (ys[idx] - m) * rs * gamma[r] + beta[r];
}

__global__ void norm_sig_kernel(float* __restrict__ yg,
                                const float* __restrict__ gamma,
                                const float* __restrict__ beta) {
    int idx = blockIdx.x * 256 + threadIdx.x;
    int b = idx / (T_ * N_ * C_);
    int r = idx % (T_ * N_ * C_);
    float m = g_stats[b * 4 + 2];
    float rs = g_stats[b * 4 + 3];
    yg[idx] = (yg[idx] - m) * rs * gamma[r] + beta[r];
}

// ---------------- launch ----------------
extern "C" void kernel_launch(void* const* d_in, const int* in_sizes, int n_in,
                              void* d_out, int out_size) {
    const float* graph_state  = (const float*)d_in[0];
    const float* graph_signal = (const float*)d_in[1];
    const float* adj          = (const float*)d_in[2];
    const float* Wq           = (const float*)d_in[3];
    const float* bq           = (const float*)d_in[4];
    const float* Wk           = (const float*)d_in[5];
    const float* bk           = (const float*)d_in[6];
    const float* Kg           = (const float*)d_in[7];
    const float* bg           = (const float*)d_in[8];
    const float* Ws           = (const float*)d_in[9];
    const float* bs           = (const float*)d_in[10];
    const float* Wf           = (const float*)d_in[11];
    const float* bf           = (const float*)d_in[12];
    const float* gs_gamma     = (const float*)d_in[13];
    const float* gs_beta      = (const float*)d_in[14];
    const float* sg_gamma     = (const float*)d_in[15];
    const float* sg_beta      = (const float*)d_in[16];

    float* out_state  = (float*)d_out;                 // [B,T,N]
    float* out_signal = out_state + BT_ * N_;          // [B,T,N,C]

    qk_kernel<<<BT_, HD_>>>(graph_state, Wq, bq, Wk, bk);
    attw_kernel<<<H_ * B_, 160>>>();
    agg_kernel<<<dim3(N_ / 128, BT_), 256>>>(adj, graph_signal);
    v_kernel<<<dim3(N_ / 128, HD_ / 64, BT_), 256>>>(Kg, bg);
    upd_kernel<<<dim3(HD_ / 128, N_, B_), 128>>>();
    sigproj_kernel<<<(BT_ * N_) / 128, 256>>>(Wf, bf, graph_signal, out_signal);
    stateproj_kernel<<<(BT_ * N_) / 8, 256>>>(Ws, bs, graph_state, out_state);
    red_state_kernel<<<B_, 256>>>(out_state);
    red_sig1_kernel<<<dim3(96, B_), 256>>>(out_signal);
    red_sig2_kernel<<<B_, 128>>>();
    norm_state_kernel<<<(BT_ * N_) / 256, 256>>>(out_state, gs_gamma, gs_beta);
    norm_sig_kernel<<<(BT_ * N_ * C_) / 256, 256>>>(out_signal, sg_gamma, sg_beta);
}